// round 10
// baseline (speedup 1.0000x reference)
#include <cuda_runtime.h>
#include <math.h>

// Problem constants
#define NPTS   30000
#define CDIM   128
#define SDIM   16      // neighbors
#define HDIM   8       // heads
#define DDIM   16      // dims per head
#define OSDIM  16      // O / SHARE
#define EPSLN  1e-5f

#define MTILES 235                 // ceil(30000/128)
#define NPAD   (MTILES * 128)      // 30080
#define GEMM_BLOCKS (MTILES * 3)
#define PE_BLOCKS   ((NPTS * SDIM + 255) / 256)

// dynamic smem layout for the GEMM part (float2 units)
#define SX_ELEMS (2 * 128 * 16)        // [stage][row][k]
#define SW_ELEMS (2 * 16 * 132)        // [stage][k][n] padded
#define SMEM_BYTES ((SX_ELEMS + SW_ELEMS) * (int)sizeof(float2))

// Scratch (no cudaMalloc allowed)
__device__ float  g_q[NPTS * CDIM];
__device__ float  g_k[NPTS * CDIM];
__device__ float  g_v[NPTS * CDIM];
__device__ float4 g_a3[NPTS * SDIM];        // relu(ln(pr@Wp1+bp1)) per (n,s)
__device__ float2 g_ws[3 * CDIM * CDIM];    // pre-split (hi,lo) of Wq,Wk,Wv
__device__ float2 g_xs[NPAD * CDIM];        // pre-split (hi,lo) of x, zero-padded

// ---------------------------------------------------------------------------
// tf32 helpers
// ---------------------------------------------------------------------------
__device__ __forceinline__ unsigned tf32_rna(float v) {
    unsigned r;
    asm("cvt.rna.tf32.f32 %0, %1;" : "=r"(r) : "f"(v));
    return r;
}
__device__ __forceinline__ float2 tf32_split(float v) {
    const unsigned hb = tf32_rna(v);
    const float hf = __uint_as_float(hb);
    const unsigned lb = tf32_rna(v - hf);
    return make_float2(hf, __uint_as_float(lb));
}

__device__ __forceinline__ void mma_tf32(float* d, const unsigned* a,
                                         unsigned b0, unsigned b1) {
    asm volatile(
        "mma.sync.aligned.m16n8k8.row.col.f32.tf32.tf32.f32 "
        "{%0,%1,%2,%3}, {%4,%5,%6,%7}, {%8,%9}, {%0,%1,%2,%3};"
        : "+f"(d[0]), "+f"(d[1]), "+f"(d[2]), "+f"(d[3])
        : "r"(a[0]), "r"(a[1]), "r"(a[2]), "r"(a[3]), "r"(b0), "r"(b1));
}

__device__ __forceinline__ void cp_async16(void* smem_dst, const void* gmem_src) {
    unsigned s = (unsigned)__cvta_generic_to_shared(smem_dst);
    asm volatile("cp.async.ca.shared.global [%0], [%1], 16;\n"
                 :: "r"(s), "l"(gmem_src));
}

// ---------------------------------------------------------------------------
// prep: split W (3x128x128) and x (padded 30080x128) into (hi,lo) tf32 pairs
// ---------------------------------------------------------------------------
__global__ __launch_bounds__(256) void prep(
    const float* __restrict__ x,
    const float* __restrict__ Wq, const float* __restrict__ Wk,
    const float* __restrict__ Wv)
{
    const int t = blockIdx.x * 256 + threadIdx.x;
    const int NW = 3 * CDIM * CDIM;
    if (t < NW) {
        const int mat = t / (CDIM * CDIM);
        const int e   = t - mat * CDIM * CDIM;
        const float v = (mat == 0) ? Wq[e] : (mat == 1) ? Wk[e] : Wv[e];
        g_ws[t] = tf32_split(v);
        return;
    }
    const int e = t - NW;
    if (e >= NPAD * CDIM) return;
    const int row = e >> 7;
    g_xs[e] = (row < NPTS) ? tf32_split(x[e]) : make_float2(0.f, 0.f);
}

// ---------------------------------------------------------------------------
// Combined mid kernel:
//   blocks [0, GEMM_BLOCKS)          : tf32 QKV GEMM tiles (dynamic smem)
//   blocks [GEMM_BLOCKS, +PE_BLOCKS) : positional precompute (a3)
// ---------------------------------------------------------------------------
__global__ __launch_bounds__(256, 2) void mid_fused(
    const float* __restrict__ bq, const float* __restrict__ bk,
    const float* __restrict__ bv,
    const float* __restrict__ p,  const int* __restrict__ idx,
    const float* __restrict__ Wp1, const float* __restrict__ bp1,
    const float* __restrict__ gp,  const float* __restrict__ betap)
{
    const int bid = blockIdx.x;
    const int tid = threadIdx.x;

    if (bid >= GEMM_BLOCKS) {
        // ---------------- positional precompute ----------------
        const int t = (bid - GEMM_BLOCKS) * 256 + tid;
        if (t >= NPTS * SDIM) return;
        const int n = t >> 4;
        const int j = idx[t];

        const float pr0 = p[j * 3 + 0] - p[n * 3 + 0];
        const float pr1 = p[j * 3 + 1] - p[n * 3 + 1];
        const float pr2 = p[j * 3 + 2] - p[n * 3 + 2];

        float t0 = fmaf(pr2, Wp1[6], fmaf(pr1, Wp1[3], fmaf(pr0, Wp1[0], bp1[0])));
        float t1 = fmaf(pr2, Wp1[7], fmaf(pr1, Wp1[4], fmaf(pr0, Wp1[1], bp1[1])));
        float t2 = fmaf(pr2, Wp1[8], fmaf(pr1, Wp1[5], fmaf(pr0, Wp1[2], bp1[2])));
        const float mp  = (t0 + t1 + t2) * (1.f / 3.f);
        const float e0 = t0 - mp, e1 = t1 - mp, e2 = t2 - mp;
        const float vp  = (e0 * e0 + e1 * e1 + e2 * e2) * (1.f / 3.f);
        const float ivp = rsqrtf(vp + EPSLN);
        const float a0 = fmaxf(fmaf(e0 * ivp, gp[0], betap[0]), 0.f);
        const float a1 = fmaxf(fmaf(e1 * ivp, gp[1], betap[1]), 0.f);
        const float a2 = fmaxf(fmaf(e2 * ivp, gp[2], betap[2]), 0.f);
        g_a3[t] = make_float4(a0, a1, a2, 0.f);
        return;
    }

    // ---------------- tf32 hi/lo GEMM tile, K-chunk = 16 ----------------
    extern __shared__ float2 smem[];
    float2* sx = smem;                 // [2][128][16]
    float2* sw = smem + SX_ELEMS;      // [2][16][132]

    const int mat   = bid % 3;
    const int mtile = bid / 3;
    const int row0  = mtile * 128;

    const float* __restrict__ bias = (mat == 0) ? bq : (mat == 1) ? bk : bv;
    float* __restrict__ out        = (mat == 0) ? g_q : (mat == 1) ? g_k : g_v;
    const float2* __restrict__ Ws  = g_ws + (size_t)mat * CDIM * CDIM;
    const float2* __restrict__ Xs  = g_xs + (size_t)row0 * CDIM;

    const int lane   = tid & 31;
    const int wid    = tid >> 5;
    const int warp_m = wid & 3;
    const int warp_n = wid >> 2;
    const int lg  = lane >> 2;
    const int lt  = lane & 3;

    float d[2][8][4];
#pragma unroll
    for (int g = 0; g < 2; g++)
#pragma unroll
        for (int nb = 0; nb < 8; nb++)
#pragma unroll
            for (int c = 0; c < 4; c++) d[g][nb][c] = 0.f;

    // staging: per stage, x = 128 rows x 16 k (1024 cp16), w = 16 k x 128 n (1024 cp16)
    // each thread: 4 x-cp + 4 w-cp
    auto stage = [&](int st, int k0) {
#pragma unroll
        for (int i = 0; i < 4; i++) {
            const int li   = tid * 4 + i;            // 0..1023
            const int xrow = li >> 3;                // 0..127
            const int xk2  = (li & 7) * 2;           // float2 pairs within 16
            cp_async16(&sx[(st * 128 + xrow) * 16 + xk2],
                       Xs + (size_t)xrow * CDIM + k0 + xk2);
            const int wk   = li >> 6;                // 0..15
            const int wn2  = (li & 63) * 2;          // 0..126
            cp_async16(&sw[(st * 16 + wk) * 132 + wn2],
                       Ws + (size_t)(k0 + wk) * CDIM + wn2);
        }
        asm volatile("cp.async.commit_group;");
    };

    // prologue
    stage(0, 0);
    asm volatile("cp.async.wait_group 0;");
    __syncthreads();

#pragma unroll 1
    for (int c = 0; c < 8; c++) {
        const int cur = c & 1;
        const bool more = (c < 7);
        if (more) stage(cur ^ 1, (c + 1) * 16);

        // compute on stage cur: two k8 sub-chunks
#pragma unroll
        for (int ks = 0; ks < 2; ks++) {
            const int kb = ks * 8;
            unsigned a_hi[2][4], a_lo[2][4];
#pragma unroll
            for (int g = 0; g < 2; g++) {
                const int rb = warp_m * 32 + g * 16;
                const float2 v0 = sx[(cur * 128 + rb + lg    ) * 16 + kb + lt    ];
                const float2 v1 = sx[(cur * 128 + rb + lg + 8) * 16 + kb + lt    ];
                const float2 v2 = sx[(cur * 128 + rb + lg    ) * 16 + kb + lt + 4];
                const float2 v3 = sx[(cur * 128 + rb + lg + 8) * 16 + kb + lt + 4];
                a_hi[g][0] = __float_as_uint(v0.x); a_lo[g][0] = __float_as_uint(v0.y);
                a_hi[g][1] = __float_as_uint(v1.x); a_lo[g][1] = __float_as_uint(v1.y);
                a_hi[g][2] = __float_as_uint(v2.x); a_lo[g][2] = __float_as_uint(v2.y);
                a_hi[g][3] = __float_as_uint(v3.x); a_lo[g][3] = __float_as_uint(v3.y);
            }
#pragma unroll
            for (int nb = 0; nb < 8; nb++) {
                const int ncol = warp_n * 64 + nb * 8 + lg;
                const float2 b0v = sw[(cur * 16 + kb + lt    ) * 132 + ncol];
                const float2 b1v = sw[(cur * 16 + kb + lt + 4) * 132 + ncol];
                const unsigned bh0 = __float_as_uint(b0v.x), bl0 = __float_as_uint(b0v.y);
                const unsigned bh1 = __float_as_uint(b1v.x), bl1 = __float_as_uint(b1v.y);
#pragma unroll
                for (int g = 0; g < 2; g++) {
                    mma_tf32(d[g][nb], a_hi[g], bh0, bh1);   // hi*hi
                    mma_tf32(d[g][nb], a_hi[g], bl0, bl1);   // hi*lo
                    mma_tf32(d[g][nb], a_lo[g], bh0, bh1);   // lo*hi
                }
            }
        }

        if (more) asm volatile("cp.async.wait_group 0;");
        __syncthreads();
    }

    // ---- epilogue: add bias, write ----
#pragma unroll
    for (int nb = 0; nb < 8; nb++) {
        const int col = warp_n * 64 + nb * 8 + lt * 2;
        const float2 bs = *(const float2*)(bias + col);
#pragma unroll
        for (int g = 0; g < 2; g++) {
            const int rbase = row0 + warp_m * 32 + g * 16 + lg;
            if (rbase < NPTS) {
                float2 o = make_float2(d[g][nb][0] + bs.x, d[g][nb][1] + bs.y);
                *(float2*)(out + (size_t)rbase * CDIM + col) = o;
            }
            if (rbase + 8 < NPTS) {
                float2 o = make_float2(d[g][nb][2] + bs.x, d[g][nb][3] + bs.y);
                *(float2*)(out + (size_t)(rbase + 8) * CDIM + col) = o;
            }
        }
    }
}

// ---------------------------------------------------------------------------
// quad (4-lane) reduction helper
// ---------------------------------------------------------------------------
__device__ __forceinline__ float quadsum(float v) {
    v += __shfl_xor_sync(0xffffffffu, v, 1, 4);
    v += __shfl_xor_sync(0xffffffffu, v, 2, 4);
    return v;
}

// ---------------------------------------------------------------------------
// Fused point-transformer kernel, 4-token batched. (unchanged from R5)
// ---------------------------------------------------------------------------
__global__ __launch_bounds__(256, 3) void pt_fused(
    const int*   __restrict__ idx,
    const float* __restrict__ Wp2, const float* __restrict__ bp2,
    const float* __restrict__ gw1, const float* __restrict__ betaw1,
    const float* __restrict__ Ww1, const float* __restrict__ bw1,
    const float* __restrict__ gw2, const float* __restrict__ betaw2,
    const float* __restrict__ Ww2, const float* __restrict__ bw2,
    float* __restrict__ out)
{
    __shared__ float sWw1[16][16];
    __shared__ float sWw2[16][16];
    __shared__ int   sidx[8][SDIM];
    __shared__ float slog[8][SDIM][HDIM];
    __shared__ float sa[8][4][HDIM][16];

    const int tid  = threadIdx.x;
    const int pt   = tid >> 5;
    const int lane = tid & 31;
    const int n    = blockIdx.x * 8 + pt;
    const int ch4  = lane * 4;
    const int qq   = lane & 3;
    const int d4   = qq * 4;
    const int hh   = lane >> 2;

    {
        float* w1f = &sWw1[0][0];
        float* w2f = &sWw2[0][0];
        w1f[tid] = Ww1[tid];
        w2f[tid] = Ww2[tid];
    }
    if (lane < SDIM) sidx[pt][lane] = idx[n * SDIM + lane];
    __syncthreads();

    const float4 xq4   = *(const float4*)(g_q + (size_t)n * CDIM + ch4);
    const float4 wp2c0 = *(const float4*)(Wp2 + 0 * CDIM + ch4);
    const float4 wp2c1 = *(const float4*)(Wp2 + 1 * CDIM + ch4);
    const float4 wp2c2 = *(const float4*)(Wp2 + 2 * CDIM + ch4);
    const float4 bp24  = *(const float4*)(bp2 + ch4);
    const float4 g14   = *(const float4*)(gw1    + d4);
    const float4 be14  = *(const float4*)(betaw1 + d4);
    const float4 b14   = *(const float4*)(bw1    + d4);
    const float4 g24   = *(const float4*)(gw2    + d4);
    const float4 be24  = *(const float4*)(betaw2 + d4);

    float4 cm;
    {
        float s0 = 0.f, s1 = 0.f, s2 = 0.f, s3 = 0.f;
#pragma unroll
        for (int j = 0; j < 4; j++) {
            const float4 v0 = *(const float4*)&sWw2[d4 + 0][j * 4];
            const float4 v1 = *(const float4*)&sWw2[d4 + 1][j * 4];
            const float4 v2 = *(const float4*)&sWw2[d4 + 2][j * 4];
            const float4 v3 = *(const float4*)&sWw2[d4 + 3][j * 4];
            s0 += v0.x + v0.y + v0.z + v0.w;
            s1 += v1.x + v1.y + v1.z + v1.w;
            s2 += v2.x + v2.y + v2.z + v2.w;
            s3 += v3.x + v3.y + v3.z + v3.w;
        }
        cm = make_float4(s0 * (1.f / 16.f), s1 * (1.f / 16.f),
                         s2 * (1.f / 16.f), s3 * (1.f / 16.f));
    }
    float mbw2;
    {
        const float4 b2 = *(const float4*)(bw2 + d4);
        mbw2 = quadsum(b2.x + b2.y + b2.z + b2.w) * (1.f / 16.f);
    }

    const int sslot = ((qq + hh) & 3) * 4;

#pragma unroll 1
    for (int s = 0; s < SDIM; s += 4) {
        float4 kg[4], a3[4];
#pragma unroll
        for (int u = 0; u < 4; u++) {
            const int j = sidx[pt][s + u];
            kg[u] = *(const float4*)(g_k + (size_t)j * CDIM + ch4);
            a3[u] = g_a3[n * SDIM + s + u];
        }

        float4 av[4];
#pragma unroll
        for (int u = 0; u < 4; u++) {
            float4 r;
            r.x = kg[u].x + fmaf(a3[u].x, wp2c0.x, fmaf(a3[u].y, wp2c1.x, fmaf(a3[u].z, wp2c2.x, bp24.x))) - xq4.x;
            r.y = kg[u].y + fmaf(a3[u].x, wp2c0.y, fmaf(a3[u].y, wp2c1.y, fmaf(a3[u].z, wp2c2.y, bp24.y))) - xq4.y;
            r.z = kg[u].z + fmaf(a3[u].x, wp2c0.z, fmaf(a3[u].y, wp2c1.z, fmaf(a3[u].z, wp2c2.z, bp24.z))) - xq4.z;
            r.w = kg[u].w + fmaf(a3[u].x, wp2c0.w, fmaf(a3[u].y, wp2c1.w, fmaf(a3[u].z, wp2c2.w, bp24.w))) - xq4.w;

            const float mean = quadsum(r.x + r.y + r.z + r.w) * (1.f / 16.f);
            r.x -= mean; r.y -= mean; r.z -= mean; r.w -= mean;
            const float var = quadsum(r.x * r.x + r.y * r.y + r.z * r.z + r.w * r.w) * (1.f / 16.f);
            const float inv = rsqrtf(var + EPSLN);
            av[u].x = fmaxf(fmaf(r.x * inv, g14.x, be14.x), 0.f);
            av[u].y = fmaxf(fmaf(r.y * inv, g14.y, be14.y), 0.f);
            av[u].z = fmaxf(fmaf(r.z * inv, g14.z, be14.z), 0.f);
            av[u].w = fmaxf(fmaf(r.w * inv, g14.w, be14.w), 0.f);
        }
#pragma unroll
        for (int u = 0; u < 4; u++)
            *(float4*)&sa[pt][u][hh][sslot] = av[u];
        __syncwarp();

        float4 w[4];
#pragma unroll
        for (int u = 0; u < 4; u++) w[u] = b14;
#pragma unroll
        for (int q = 0; q < 4; q++) {
            const float4 c0 = *(const float4*)&sWw1[q * 4 + 0][d4];
            const float4 c1 = *(const float4*)&sWw1[q * 4 + 1][d4];
            const float4 c2 = *(const float4*)&sWw1[q * 4 + 2][d4];
            const float4 c3 = *(const float4*)&sWw1[q * 4 + 3][d4];
            const int ps = ((q + hh) & 3) * 4;
#pragma unroll
            for (int u = 0; u < 4; u++) {
                const float4 a = *(const float4*)&sa[pt][u][hh][ps];
                w[u].x = fmaf(a.x, c0.x, fmaf(a.y, c1.x, fmaf(a.z, c2.x, fmaf(a.w, c3.x, w[u].x))));
                w[u].y = fmaf(a.x, c0.y, fmaf(a.y, c1.y, fmaf(a.z, c2.y, fmaf(a.w, c3.y, w[u].y))));
                w[u].z = fmaf(a.x, c0.z, fmaf(a.y, c1.z, fmaf(a.z, c2.z, fmaf(a.w, c3.z, w[u].z))));
                w[u].w = fmaf(a.x, c0.w, fmaf(a.y, c1.w, fmaf(a.z, c2.w, fmaf(a.w, c3.w, w[u].w))));
            }
        }
        __syncwarp();

#pragma unroll
        for (int u = 0; u < 4; u++) {
            const float m2 = quadsum(w[u].x + w[u].y + w[u].z + w[u].w) * (1.f / 16.f);
            const float fx = w[u].x - m2, fy = w[u].y - m2, fz = w[u].z - m2, fw = w[u].w - m2;
            const float v2 = quadsum(fx * fx + fy * fy + fz * fz + fw * fw) * (1.f / 16.f);
            const float i2 = rsqrtf(v2 + EPSLN);
            const float ex = fmaxf(fmaf(fx * i2, g24.x, be24.x), 0.f);
            const float ey = fmaxf(fmaf(fy * i2, g24.y, be24.y), 0.f);
            const float ez = fmaxf(fmaf(fz * i2, g24.z, be24.z), 0.f);
            const float ew = fmaxf(fmaf(fw * i2, g24.w, be24.w), 0.f);
            const float l = quadsum(fmaf(ex, cm.x, fmaf(ey, cm.y, fmaf(ez, cm.z, ew * cm.w))));
            if (qq == 0) slog[pt][s + u][hh] = l + mbw2;
        }
    }
    __syncwarp();

    float mx = -1e30f;
#pragma unroll
    for (int s = 0; s < SDIM; s++) mx = fmaxf(mx, slog[pt][s][hh]);
    float se = 0.f;
    float ev[SDIM];
#pragma unroll
    for (int s = 0; s < SDIM; s++) {
        ev[s] = __expf(slog[pt][s][hh] - mx);
        se += ev[s];
    }
    const float rse = 1.f / se;

    float4 acc = make_float4(0.f, 0.f, 0.f, 0.f);
    float A0 = 0.f, A1 = 0.f, A2 = 0.f;
#pragma unroll 2
    for (int s = 0; s < SDIM; s++) {
        const float wg = ev[s] * rse;
        const int j = sidx[pt][s];
        const float4 vg = *(const float4*)(g_v + (size_t)j * CDIM + ch4);
        const float4 a3 = g_a3[n * SDIM + s];
        acc.x = fmaf(vg.x, wg, acc.x);
        acc.y = fmaf(vg.y, wg, acc.y);
        acc.z = fmaf(vg.z, wg, acc.z);
        acc.w = fmaf(vg.w, wg, acc.w);
        A0 = fmaf(a3.x, wg, A0);
        A1 = fmaf(a3.y, wg, A1);
        A2 = fmaf(a3.z, wg, A2);
    }
    float4 o;
    o.x = acc.x + fmaf(A0, wp2c0.x, fmaf(A1, wp2c1.x, fmaf(A2, wp2c2.x, bp24.x)));
    o.y = acc.y + fmaf(A0, wp2c0.y, fmaf(A1, wp2c1.y, fmaf(A2, wp2c2.y, bp24.y)));
    o.z = acc.z + fmaf(A0, wp2c0.z, fmaf(A1, wp2c1.z, fmaf(A2, wp2c2.z, bp24.z)));
    o.w = acc.w + fmaf(A0, wp2c0.w, fmaf(A1, wp2c1.w, fmaf(A2, wp2c2.w, bp24.w)));
    *(float4*)(out + (size_t)n * CDIM + ch4) = o;
}

// ---------------------------------------------------------------------------
extern "C" void kernel_launch(void* const* d_in, const int* in_sizes, int n_in,
                              void* d_out, int out_size)
{
    const float* p      = (const float*)d_in[0];
    const float* x      = (const float*)d_in[1];
    const int*   idx    = (const int*)  d_in[2];
    const float* Wq     = (const float*)d_in[3];
    const float* bq     = (const float*)d_in[4];
    const float* Wk     = (const float*)d_in[5];
    const float* bk     = (const float*)d_in[6];
    const float* Wv     = (const float*)d_in[7];
    const float* bv     = (const float*)d_in[8];
    const float* Wp1    = (const float*)d_in[9];
    const float* bp1    = (const float*)d_in[10];
    const float* gp     = (const float*)d_in[11];
    const float* betap  = (const float*)d_in[12];
    const float* Wp2    = (const float*)d_in[13];
    const float* bp2    = (const float*)d_in[14];
    const float* gw1    = (const float*)d_in[15];
    const float* betaw1 = (const float*)d_in[16];
    const float* Ww1    = (const float*)d_in[17];
    const float* bw1    = (const float*)d_in[18];
    const float* gw2    = (const float*)d_in[19];
    const float* betaw2 = (const float*)d_in[20];
    const float* Ww2    = (const float*)d_in[21];
    const float* bw2    = (const float*)d_in[22];
    float* out = (float*)d_out;

    static bool attr_set = false;
    // Attribute set is idempotent and not a stream/alloc op; safe to repeat.
    cudaFuncSetAttribute(mid_fused, cudaFuncAttributeMaxDynamicSharedMemorySize,
                         SMEM_BYTES);
    (void)attr_set;

    const int prep_total = 3 * CDIM * CDIM + NPAD * CDIM;
    prep<<<(prep_total + 255) / 256, 256>>>(x, Wq, Wk, Wv);

    mid_fused<<<GEMM_BLOCKS + PE_BLOCKS, 256, SMEM_BYTES>>>(
        bq, bk, bv, p, idx, Wp1, bp1, gp, betap);

    pt_fused<<<NPTS / 8, 256>>>(idx,
                                Wp2, bp2,
                                gw1, betaw1, Ww1, bw1,
                                gw2, betaw2, Ww2, bw2, out);
}

// round 11
// speedup vs baseline: 1.1738x; 1.1738x over previous
#include <cuda_runtime.h>
#include <math.h>

// Problem constants
#define NPTS   30000
#define CDIM   128
#define SDIM   16      // neighbors
#define HDIM   8       // heads
#define DDIM   16      // dims per head
#define OSDIM  16      // O / SHARE
#define EPSLN  1e-5f

#define MTILES 235                 // ceil(30000/128)
#define GEMM_BLOCKS (MTILES * 3)
#define PE_BLOCKS   ((NPTS * SDIM + 255) / 256)

// dynamic smem for GEMM: sx = 2*128*16 floats, sw = 2*16*132 float2
#define SX_FLOATS (2 * 128 * 16)
#define SW_F2     (2 * 16 * 132)
#define SMEM_BYTES (SX_FLOATS * 4 + SW_F2 * 8)

// Scratch (no cudaMalloc allowed)
__device__ float  g_q[NPTS * CDIM];
__device__ float  g_k[NPTS * CDIM];
__device__ float  g_v[NPTS * CDIM];
__device__ float4 g_a3[NPTS * SDIM];        // relu(ln(pr@Wp1+bp1)) per (n,s)
__device__ float2 g_ws[3 * CDIM * CDIM];    // pre-split (hi,lo) of Wq,Wk,Wv

// ---------------------------------------------------------------------------
// tf32 helpers
// ---------------------------------------------------------------------------
__device__ __forceinline__ unsigned tf32_rna(float v) {
    unsigned r;
    asm("cvt.rna.tf32.f32 %0, %1;" : "=r"(r) : "f"(v));
    return r;
}
__device__ __forceinline__ float2 tf32_split(float v) {
    const unsigned hb = tf32_rna(v);
    const float hf = __uint_as_float(hb);
    const unsigned lb = tf32_rna(v - hf);
    return make_float2(hf, __uint_as_float(lb));
}

__device__ __forceinline__ void mma_tf32(float* d, const unsigned* a,
                                         unsigned b0, unsigned b1) {
    asm volatile(
        "mma.sync.aligned.m16n8k8.row.col.f32.tf32.tf32.f32 "
        "{%0,%1,%2,%3}, {%4,%5,%6,%7}, {%8,%9}, {%0,%1,%2,%3};"
        : "+f"(d[0]), "+f"(d[1]), "+f"(d[2]), "+f"(d[3])
        : "r"(a[0]), "r"(a[1]), "r"(a[2]), "r"(a[3]), "r"(b0), "r"(b1));
}

__device__ __forceinline__ void cp_async16(void* smem_dst, const void* gmem_src) {
    unsigned s = (unsigned)__cvta_generic_to_shared(smem_dst);
    asm volatile("cp.async.ca.shared.global [%0], [%1], 16;\n"
                 :: "r"(s), "l"(gmem_src));
}

// ---------------------------------------------------------------------------
// W split precompute (small: 3*128*128 elements)
// ---------------------------------------------------------------------------
__global__ __launch_bounds__(256) void w_split(
    const float* __restrict__ Wq, const float* __restrict__ Wk,
    const float* __restrict__ Wv)
{
    const int i = blockIdx.x * 256 + threadIdx.x;
    if (i >= 3 * CDIM * CDIM) return;
    const int mat = i / (CDIM * CDIM);
    const int e   = i - mat * CDIM * CDIM;
    const float v = (mat == 0) ? Wq[e] : (mat == 1) ? Wk[e] : Wv[e];
    g_ws[i] = tf32_split(v);
}

// ---------------------------------------------------------------------------
// Combined mid kernel:
//   blocks [0, GEMM_BLOCKS)          : tf32 QKV GEMM tiles (x tf32, W hi/lo)
//   blocks [GEMM_BLOCKS, +PE_BLOCKS) : positional precompute (a3)
// ---------------------------------------------------------------------------
__global__ __launch_bounds__(256, 2) void mid_fused(
    const float* __restrict__ x,
    const float* __restrict__ bq, const float* __restrict__ bk,
    const float* __restrict__ bv,
    const float* __restrict__ p,  const int* __restrict__ idx,
    const float* __restrict__ Wp1, const float* __restrict__ bp1,
    const float* __restrict__ gp,  const float* __restrict__ betap)
{
    const int bid = blockIdx.x;
    const int tid = threadIdx.x;

    if (bid >= GEMM_BLOCKS) {
        // ---------------- positional precompute ----------------
        const int t = (bid - GEMM_BLOCKS) * 256 + tid;
        if (t >= NPTS * SDIM) return;
        const int n = t >> 4;
        const int j = idx[t];

        const float pr0 = p[j * 3 + 0] - p[n * 3 + 0];
        const float pr1 = p[j * 3 + 1] - p[n * 3 + 1];
        const float pr2 = p[j * 3 + 2] - p[n * 3 + 2];

        float t0 = fmaf(pr2, Wp1[6], fmaf(pr1, Wp1[3], fmaf(pr0, Wp1[0], bp1[0])));
        float t1 = fmaf(pr2, Wp1[7], fmaf(pr1, Wp1[4], fmaf(pr0, Wp1[1], bp1[1])));
        float t2 = fmaf(pr2, Wp1[8], fmaf(pr1, Wp1[5], fmaf(pr0, Wp1[2], bp1[2])));
        const float mp  = (t0 + t1 + t2) * (1.f / 3.f);
        const float e0 = t0 - mp, e1 = t1 - mp, e2 = t2 - mp;
        const float vp  = (e0 * e0 + e1 * e1 + e2 * e2) * (1.f / 3.f);
        const float ivp = rsqrtf(vp + EPSLN);
        const float a0 = fmaxf(fmaf(e0 * ivp, gp[0], betap[0]), 0.f);
        const float a1 = fmaxf(fmaf(e1 * ivp, gp[1], betap[1]), 0.f);
        const float a2 = fmaxf(fmaf(e2 * ivp, gp[2], betap[2]), 0.f);
        g_a3[t] = make_float4(a0, a1, a2, 0.f);
        return;
    }

    // ---------------- GEMM tile: x(tf32) @ W(hi+lo), K-chunk 16 ----------------
    extern __shared__ float smf[];
    float*  sx = smf;                          // [2][128][16] (hi only)
    float2* sw = (float2*)(smf + SX_FLOATS);   // [2][16][132]

    const int mat   = bid % 3;
    const int mtile = bid / 3;
    const int row0  = mtile * 128;

    const float* __restrict__ bias = (mat == 0) ? bq : (mat == 1) ? bk : bv;
    float* __restrict__ out        = (mat == 0) ? g_q : (mat == 1) ? g_k : g_v;
    const float2* __restrict__ Ws  = g_ws + (size_t)mat * CDIM * CDIM;

    const int lane   = tid & 31;
    const int wid    = tid >> 5;
    const int warp_m = wid & 3;
    const int warp_n = wid >> 2;
    const int lg  = lane >> 2;
    const int lt  = lane & 3;

    const int xrow = tid >> 1;               // 0..127
    const int xko  = (tid & 1) * 8;          // 0 or 8
    const bool xvalid = (row0 + xrow) < NPTS;
    const float* xbase = x + (size_t)(row0 + xrow) * CDIM + xko;

    float d[2][8][4];
#pragma unroll
    for (int g = 0; g < 2; g++)
#pragma unroll
        for (int nb = 0; nb < 8; nb++)
#pragma unroll
            for (int c = 0; c < 4; c++) d[g][nb][c] = 0.f;

    auto stage_w = [&](int st, int k0) {
#pragma unroll
        for (int i = 0; i < 4; i++) {
            const int li  = tid * 4 + i;           // 0..1023
            const int wk  = li >> 6;               // 0..15
            const int wn2 = (li & 63) * 2;         // 0..126
            cp_async16(&sw[(st * 16 + wk) * 132 + wn2],
                       Ws + (size_t)(k0 + wk) * CDIM + wn2);
        }
        asm volatile("cp.async.commit_group;");
    };
    auto cvt4 = [&](float4 v) {
        return make_float4(__uint_as_float(tf32_rna(v.x)),
                           __uint_as_float(tf32_rna(v.y)),
                           __uint_as_float(tf32_rna(v.z)),
                           __uint_as_float(tf32_rna(v.w)));
    };
    auto store_x = [&](int st, float4 xa, float4 xb) {
        *(float4*)&sx[(st * 128 + xrow) * 16 + xko    ] = cvt4(xa);
        *(float4*)&sx[(st * 128 + xrow) * 16 + xko + 4] = cvt4(xb);
    };

    // prologue
    stage_w(0, 0);
    {
        float4 xa = make_float4(0.f, 0.f, 0.f, 0.f), xb = xa;
        if (xvalid) { xa = *(const float4*)(xbase); xb = *(const float4*)(xbase + 4); }
        store_x(0, xa, xb);
    }
    asm volatile("cp.async.wait_group 0;");
    __syncthreads();

#pragma unroll 1
    for (int c = 0; c < 8; c++) {
        const int cur = c & 1;
        const bool more = (c < 7);

        float4 xa, xb;
        if (more) {
            stage_w(cur ^ 1, (c + 1) * 16);
            xa = make_float4(0.f, 0.f, 0.f, 0.f); xb = xa;
            if (xvalid) {
                xa = *(const float4*)(xbase + (c + 1) * 16);
                xb = *(const float4*)(xbase + (c + 1) * 16 + 4);
            }
        }

        // compute on stage cur: two k8 sub-chunks, 2-term MMA
#pragma unroll
        for (int ks = 0; ks < 2; ks++) {
            const int kb = ks * 8;
            unsigned a_hi[2][4];
#pragma unroll
            for (int g = 0; g < 2; g++) {
                const int rb = warp_m * 32 + g * 16;
                a_hi[g][0] = __float_as_uint(sx[(cur * 128 + rb + lg    ) * 16 + kb + lt    ]);
                a_hi[g][1] = __float_as_uint(sx[(cur * 128 + rb + lg + 8) * 16 + kb + lt    ]);
                a_hi[g][2] = __float_as_uint(sx[(cur * 128 + rb + lg    ) * 16 + kb + lt + 4]);
                a_hi[g][3] = __float_as_uint(sx[(cur * 128 + rb + lg + 8) * 16 + kb + lt + 4]);
            }
#pragma unroll
            for (int nb = 0; nb < 8; nb++) {
                const int ncol = warp_n * 64 + nb * 8 + lg;
                const float2 b0v = sw[(cur * 16 + kb + lt    ) * 132 + ncol];
                const float2 b1v = sw[(cur * 16 + kb + lt + 4) * 132 + ncol];
                const unsigned bh0 = __float_as_uint(b0v.x), bl0 = __float_as_uint(b0v.y);
                const unsigned bh1 = __float_as_uint(b1v.x), bl1 = __float_as_uint(b1v.y);
#pragma unroll
                for (int g = 0; g < 2; g++) {
                    mma_tf32(d[g][nb], a_hi[g], bh0, bh1);   // x * W_hi
                    mma_tf32(d[g][nb], a_hi[g], bl0, bl1);   // x * W_lo
                }
            }
        }

        if (more) {
            store_x(cur ^ 1, xa, xb);
            asm volatile("cp.async.wait_group 0;");
        }
        __syncthreads();
    }

    // ---- epilogue: add bias, write ----
#pragma unroll
    for (int nb = 0; nb < 8; nb++) {
        const int col = warp_n * 64 + nb * 8 + lt * 2;
        const float2 bs = *(const float2*)(bias + col);
#pragma unroll
        for (int g = 0; g < 2; g++) {
            const int rbase = row0 + warp_m * 32 + g * 16 + lg;
            if (rbase < NPTS) {
                float2 o = make_float2(d[g][nb][0] + bs.x, d[g][nb][1] + bs.y);
                *(float2*)(out + (size_t)rbase * CDIM + col) = o;
            }
            if (rbase + 8 < NPTS) {
                float2 o = make_float2(d[g][nb][2] + bs.x, d[g][nb][3] + bs.y);
                *(float2*)(out + (size_t)(rbase + 8) * CDIM + col) = o;
            }
        }
    }
}

// ---------------------------------------------------------------------------
// Fused point-transformer kernel, 4-token batched; LN reductions single-pass
// (mean + E[x^2]) with shuffles batched across tokens for ILP.
// ---------------------------------------------------------------------------
__global__ __launch_bounds__(256, 3) void pt_fused(
    const int*   __restrict__ idx,
    const float* __restrict__ Wp2, const float* __restrict__ bp2,
    const float* __restrict__ gw1, const float* __restrict__ betaw1,
    const float* __restrict__ Ww1, const float* __restrict__ bw1,
    const float* __restrict__ gw2, const float* __restrict__ betaw2,
    const float* __restrict__ Ww2, const float* __restrict__ bw2,
    float* __restrict__ out)
{
    __shared__ float sWw1[16][16];
    __shared__ float sWw2[16][16];
    __shared__ int   sidx[8][SDIM];
    __shared__ float slog[8][SDIM][HDIM];
    __shared__ float sa[8][4][HDIM][16];

    const int tid  = threadIdx.x;
    const int pt   = tid >> 5;
    const int lane = tid & 31;
    const int n    = blockIdx.x * 8 + pt;
    const int ch4  = lane * 4;
    const int qq   = lane & 3;
    const int d4   = qq * 4;
    const int hh   = lane >> 2;
    const unsigned FULL = 0xffffffffu;

    {
        float* w1f = &sWw1[0][0];
        float* w2f = &sWw2[0][0];
        w1f[tid] = Ww1[tid];
        w2f[tid] = Ww2[tid];
    }
    if (lane < SDIM) sidx[pt][lane] = idx[n * SDIM + lane];
    __syncthreads();

    const float4 xq4   = *(const float4*)(g_q + (size_t)n * CDIM + ch4);
    const float4 wp2c0 = *(const float4*)(Wp2 + 0 * CDIM + ch4);
    const float4 wp2c1 = *(const float4*)(Wp2 + 1 * CDIM + ch4);
    const float4 wp2c2 = *(const float4*)(Wp2 + 2 * CDIM + ch4);
    const float4 bp24  = *(const float4*)(bp2 + ch4);
    const float4 g14   = *(const float4*)(gw1    + d4);
    const float4 be14  = *(const float4*)(betaw1 + d4);
    const float4 b14   = *(const float4*)(bw1    + d4);
    const float4 g24   = *(const float4*)(gw2    + d4);
    const float4 be24  = *(const float4*)(betaw2 + d4);

    float4 cm;
    {
        float s0 = 0.f, s1 = 0.f, s2 = 0.f, s3 = 0.f;
#pragma unroll
        for (int j = 0; j < 4; j++) {
            const float4 v0 = *(const float4*)&sWw2[d4 + 0][j * 4];
            const float4 v1 = *(const float4*)&sWw2[d4 + 1][j * 4];
            const float4 v2 = *(const float4*)&sWw2[d4 + 2][j * 4];
            const float4 v3 = *(const float4*)&sWw2[d4 + 3][j * 4];
            s0 += v0.x + v0.y + v0.z + v0.w;
            s1 += v1.x + v1.y + v1.z + v1.w;
            s2 += v2.x + v2.y + v2.z + v2.w;
            s3 += v3.x + v3.y + v3.z + v3.w;
        }
        cm = make_float4(s0 * (1.f / 16.f), s1 * (1.f / 16.f),
                         s2 * (1.f / 16.f), s3 * (1.f / 16.f));
    }
    float mbw2;
    {
        const float4 b2 = *(const float4*)(bw2 + d4);
        float sb = b2.x + b2.y + b2.z + b2.w;
        sb += __shfl_xor_sync(FULL, sb, 1, 4);
        sb += __shfl_xor_sync(FULL, sb, 2, 4);
        mbw2 = sb * (1.f / 16.f);
    }

    const int sslot = ((qq + hh) & 3) * 4;

#pragma unroll 1
    for (int s = 0; s < SDIM; s += 4) {
        float4 r[4], a3[4];
#pragma unroll
        for (int u = 0; u < 4; u++) {
            const int j = sidx[pt][s + u];
            r[u]  = *(const float4*)(g_k + (size_t)j * CDIM + ch4);
            a3[u] = g_a3[n * SDIM + s + u];
        }

        // r = kg + pe - xq ; accumulate sum & sumsq
        float sm[4], sq[4];
#pragma unroll
        for (int u = 0; u < 4; u++) {
            r[u].x += fmaf(a3[u].x, wp2c0.x, fmaf(a3[u].y, wp2c1.x, fmaf(a3[u].z, wp2c2.x, bp24.x))) - xq4.x;
            r[u].y += fmaf(a3[u].x, wp2c0.y, fmaf(a3[u].y, wp2c1.y, fmaf(a3[u].z, wp2c2.y, bp24.y))) - xq4.y;
            r[u].z += fmaf(a3[u].x, wp2c0.z, fmaf(a3[u].y, wp2c1.z, fmaf(a3[u].z, wp2c2.z, bp24.z))) - xq4.z;
            r[u].w += fmaf(a3[u].x, wp2c0.w, fmaf(a3[u].y, wp2c1.w, fmaf(a3[u].z, wp2c2.w, bp24.w))) - xq4.w;
            sm[u] = r[u].x + r[u].y + r[u].z + r[u].w;
            sq[u] = r[u].x * r[u].x + r[u].y * r[u].y + r[u].z * r[u].z + r[u].w * r[u].w;
        }
        // batched shuffles (8 independent chains)
#pragma unroll
        for (int u = 0; u < 4; u++) { sm[u] += __shfl_xor_sync(FULL, sm[u], 1, 4);
                                      sq[u] += __shfl_xor_sync(FULL, sq[u], 1, 4); }
#pragma unroll
        for (int u = 0; u < 4; u++) { sm[u] += __shfl_xor_sync(FULL, sm[u], 2, 4);
                                      sq[u] += __shfl_xor_sync(FULL, sq[u], 2, 4); }
#pragma unroll
        for (int u = 0; u < 4; u++) {
            const float mean = sm[u] * (1.f / 16.f);
            const float var  = fmaf(-mean, mean, sq[u] * (1.f / 16.f));
            const float inv  = rsqrtf(var + EPSLN);
            float4 a;
            a.x = fmaxf(fmaf((r[u].x - mean) * inv, g14.x, be14.x), 0.f);
            a.y = fmaxf(fmaf((r[u].y - mean) * inv, g14.y, be14.y), 0.f);
            a.z = fmaxf(fmaf((r[u].z - mean) * inv, g14.z, be14.z), 0.f);
            a.w = fmaxf(fmaf((r[u].w - mean) * inv, g14.w, be14.w), 0.f);
            *(float4*)&sa[pt][u][hh][sslot] = a;
        }
        __syncwarp();

        // matvec1: weights shared across all 4 tokens
        float4 w[4];
#pragma unroll
        for (int u = 0; u < 4; u++) w[u] = b14;
#pragma unroll
        for (int q = 0; q < 4; q++) {
            const float4 c0 = *(const float4*)&sWw1[q * 4 + 0][d4];
            const float4 c1 = *(const float4*)&sWw1[q * 4 + 1][d4];
            const float4 c2 = *(const float4*)&sWw1[q * 4 + 2][d4];
            const float4 c3 = *(const float4*)&sWw1[q * 4 + 3][d4];
            const int ps = ((q + hh) & 3) * 4;
#pragma unroll
            for (int u = 0; u < 4; u++) {
                const float4 a = *(const float4*)&sa[pt][u][hh][ps];
                w[u].x = fmaf(a.x, c0.x, fmaf(a.y, c1.x, fmaf(a.z, c2.x, fmaf(a.w, c3.x, w[u].x))));
                w[u].y = fmaf(a.x, c0.y, fmaf(a.y, c1.y, fmaf(a.z, c2.y, fmaf(a.w, c3.y, w[u].y))));
                w[u].z = fmaf(a.x, c0.z, fmaf(a.y, c1.z, fmaf(a.z, c2.z, fmaf(a.w, c3.z, w[u].z))));
                w[u].w = fmaf(a.x, c0.w, fmaf(a.y, c1.w, fmaf(a.z, c2.w, fmaf(a.w, c3.w, w[u].w))));
            }
        }
        __syncwarp();

        // LN2: single-pass sums, batched shuffles
#pragma unroll
        for (int u = 0; u < 4; u++) {
            sm[u] = w[u].x + w[u].y + w[u].z + w[u].w;
            sq[u] = w[u].x * w[u].x + w[u].y * w[u].y + w[u].z * w[u].z + w[u].w * w[u].w;
        }
#pragma unroll
        for (int u = 0; u < 4; u++) { sm[u] += __shfl_xor_sync(FULL, sm[u], 1, 4);
                                      sq[u] += __shfl_xor_sync(FULL, sq[u], 1, 4); }
#pragma unroll
        for (int u = 0; u < 4; u++) { sm[u] += __shfl_xor_sync(FULL, sm[u], 2, 4);
                                      sq[u] += __shfl_xor_sync(FULL, sq[u], 2, 4); }

        float l[4];
#pragma unroll
        for (int u = 0; u < 4; u++) {
            const float mean = sm[u] * (1.f / 16.f);
            const float var  = fmaf(-mean, mean, sq[u] * (1.f / 16.f));
            const float inv  = rsqrtf(var + EPSLN);
            const float ex = fmaxf(fmaf((w[u].x - mean) * inv, g24.x, be24.x), 0.f);
            const float ey = fmaxf(fmaf((w[u].y - mean) * inv, g24.y, be24.y), 0.f);
            const float ez = fmaxf(fmaf((w[u].z - mean) * inv, g24.z, be24.z), 0.f);
            const float ew = fmaxf(fmaf((w[u].w - mean) * inv, g24.w, be24.w), 0.f);
            l[u] = fmaf(ex, cm.x, fmaf(ey, cm.y, fmaf(ez, cm.z, ew * cm.w)));
        }
#pragma unroll
        for (int u = 0; u < 4; u++) l[u] += __shfl_xor_sync(FULL, l[u], 1, 4);
#pragma unroll
        for (int u = 0; u < 4; u++) l[u] += __shfl_xor_sync(FULL, l[u], 2, 4);
        if (qq == 0) {
#pragma unroll
            for (int u = 0; u < 4; u++) slog[pt][s + u][hh] = l[u] + mbw2;
        }
    }
    __syncwarp();

    // ---- softmax over S (per head, redundant across the 4 lanes) ----
    float mx = -1e30f;
#pragma unroll
    for (int s = 0; s < SDIM; s++) mx = fmaxf(mx, slog[pt][s][hh]);
    float se = 0.f;
    float ev[SDIM];
#pragma unroll
    for (int s = 0; s < SDIM; s++) {
        ev[s] = __expf(slog[pt][s][hh] - mx);
        se += ev[s];
    }
    const float rse = 1.f / se;

    // ---- pass 2: out = sum_s (v_g + pe) * w ; pe-part via A = sum_s w_s * a3_s
    float4 acc = make_float4(0.f, 0.f, 0.f, 0.f);
    float A0 = 0.f, A1 = 0.f, A2 = 0.f;
#pragma unroll 2
    for (int s = 0; s < SDIM; s++) {
        const float wg = ev[s] * rse;
        const int j = sidx[pt][s];
        const float4 vg = *(const float4*)(g_v + (size_t)j * CDIM + ch4);
        const float4 a3 = g_a3[n * SDIM + s];
        acc.x = fmaf(vg.x, wg, acc.x);
        acc.y = fmaf(vg.y, wg, acc.y);
        acc.z = fmaf(vg.z, wg, acc.z);
        acc.w = fmaf(vg.w, wg, acc.w);
        A0 = fmaf(a3.x, wg, A0);
        A1 = fmaf(a3.y, wg, A1);
        A2 = fmaf(a3.z, wg, A2);
    }
    float4 o;
    o.x = acc.x + fmaf(A0, wp2c0.x, fmaf(A1, wp2c1.x, fmaf(A2, wp2c2.x, bp24.x)));
    o.y = acc.y + fmaf(A0, wp2c0.y, fmaf(A1, wp2c1.y, fmaf(A2, wp2c2.y, bp24.y)));
    o.z = acc.z + fmaf(A0, wp2c0.z, fmaf(A1, wp2c1.z, fmaf(A2, wp2c2.z, bp24.z)));
    o.w = acc.w + fmaf(A0, wp2c0.w, fmaf(A1, wp2c1.w, fmaf(A2, wp2c2.w, bp24.w)));
    *(float4*)(out + (size_t)n * CDIM + ch4) = o;
}

// ---------------------------------------------------------------------------
extern "C" void kernel_launch(void* const* d_in, const int* in_sizes, int n_in,
                              void* d_out, int out_size)
{
    const float* p      = (const float*)d_in[0];
    const float* x      = (const float*)d_in[1];
    const int*   idx    = (const int*)  d_in[2];
    const float* Wq     = (const float*)d_in[3];
    const float* bq     = (const float*)d_in[4];
    const float* Wk     = (const float*)d_in[5];
    const float* bk     = (const float*)d_in[6];
    const float* Wv     = (const float*)d_in[7];
    const float* bv     = (const float*)d_in[8];
    const float* Wp1    = (const float*)d_in[9];
    const float* bp1    = (const float*)d_in[10];
    const float* gp     = (const float*)d_in[11];
    const float* betap  = (const float*)d_in[12];
    const float* Wp2    = (const float*)d_in[13];
    const float* bp2    = (const float*)d_in[14];
    const float* gw1    = (const float*)d_in[15];
    const float* betaw1 = (const float*)d_in[16];
    const float* Ww1    = (const float*)d_in[17];
    const float* bw1    = (const float*)d_in[18];
    const float* gw2    = (const float*)d_in[19];
    const float* betaw2 = (const float*)d_in[20];
    const float* Ww2    = (const float*)d_in[21];
    const float* bw2    = (const float*)d_in[22];
    float* out = (float*)d_out;

    cudaFuncSetAttribute(mid_fused, cudaFuncAttributeMaxDynamicSharedMemorySize,
                         SMEM_BYTES);

    w_split<<<(3 * CDIM * CDIM + 255) / 256, 256>>>(Wq, Wk, Wv);

    mid_fused<<<GEMM_BLOCKS + PE_BLOCKS, 256, SMEM_BYTES>>>(
        x, bq, bk, bv, p, idx, Wp1, bp1, gp, betap);

    pt_fused<<<NPTS / 8, 256>>>(idx,
                                Wp2, bp2,
                                gw1, betaw1, Ww1, bw1,
                                gw2, betaw2, Ww2, bw2, out);
}